// round 15
// baseline (speedup 1.0000x reference)
#include <cuda_runtime.h>
#include <cuda_fp16.h>
#include <math.h>
#include <stdint.h>

#define T_  12
#define E_  8192
#define H_  256
#define V_  800
#define B_  256
#define NB_ 8
#define M_  (T_*E_)   // 98304 messages; h has 1+M rows (row 0 = pad)

// ---------------- scratch (static device arrays; no allocs allowed) ----------
// interleaved fp16 h + hU: per row, 64 chunks of 16B = {h2(c0c1), h2(c2c3), u2(c0c1), u2(c2c3)}
__device__ uint4 g_hx[(size_t)(M_+1)*64];
__device__ float g_Ez[(size_t)V_*H_];
__device__ float g_Er[(size_t)V_*H_];
__device__ float g_Eh[(size_t)V_*H_];
__device__ float g_Eo[(size_t)V_*H_];

// fp16 operands (single-term weights; sum_h keeps hi+lo for the epilogue path)
__device__ __half g_sh_hi[(size_t)E_*H_], g_sh_lo[(size_t)E_*H_];
__device__ __half g_sg   [(size_t)E_*H_];
__device__ __half g_Wzh[H_*H_];
__device__ __half g_Whh[H_*H_];
__device__ __half g_Ur [H_*H_];

// hardware tanh (sm_75+): ~2^-11 max rel error
__device__ __forceinline__ float tanha(float x) {
    float t;
    asm("tanh.approx.f32 %0, %1;" : "=f"(t) : "f"(x));
    return t;
}
// sigmoid via tanh: sigma(x) = 0.5*tanh(x/2) + 0.5  (1 MUFU)
__device__ __forceinline__ float sigf(float x) {
    return fmaf(0.5f, tanha(0.5f * x), 0.5f);
}

// ---------------- PTX helpers -------------------------------------------------
__device__ __forceinline__ uint32_t smem_u32(const void* p) {
    return (uint32_t)__cvta_generic_to_shared(p);
}
__device__ __forceinline__ void ldsm4(uint32_t* r, uint32_t a) {
    asm volatile("ldmatrix.sync.aligned.m8n8.x4.shared.b16 {%0,%1,%2,%3},[%4];\n"
                 : "=r"(r[0]), "=r"(r[1]), "=r"(r[2]), "=r"(r[3]) : "r"(a));
}
__device__ __forceinline__ void ldsm4t(uint32_t* r, uint32_t a) {
    asm volatile("ldmatrix.sync.aligned.m8n8.x4.trans.shared.b16 {%0,%1,%2,%3},[%4];\n"
                 : "=r"(r[0]), "=r"(r[1]), "=r"(r[2]), "=r"(r[3]) : "r"(a));
}
__device__ __forceinline__ void mma16816(float* d, const uint32_t* a, const uint32_t* b) {
    asm volatile("mma.sync.aligned.m16n8k16.row.col.f32.f16.f16.f32 "
                 "{%0,%1,%2,%3},{%4,%5,%6,%7},{%8,%9},{%0,%1,%2,%3};\n"
                 : "+f"(d[0]), "+f"(d[1]), "+f"(d[2]), "+f"(d[3])
                 : "r"(a[0]), "r"(a[1]), "r"(a[2]), "r"(a[3]), "r"(b[0]), "r"(b[1]));
}
__device__ __forceinline__ void cpa16(uint32_t dst, const void* src) {
    asm volatile("cp.async.cg.shared.global [%0],[%1],16;\n" :: "r"(dst), "l"(src));
}
#define CP_COMMIT()  asm volatile("cp.async.commit_group;\n" ::: "memory")
#define CP_WAIT1()   asm volatile("cp.async.wait_group 1;\n" ::: "memory")

__device__ __forceinline__ uint32_t pack_h2(float a, float b) {
    __half2 t; t.x = __float2half_rn(a); t.y = __float2half_rn(b);
    return *reinterpret_cast<uint32_t*>(&t);
}
__device__ __forceinline__ float2 unpack_h2(uint32_t u) {
    __half2 t = *reinterpret_cast<__half2*>(&u);
    return make_float2(__half2float(t.x), __half2float(t.y));
}

// ---------------- init --------------------------------------------------------
__global__ void init_zero(float* __restrict__ h)
{
    int c = threadIdx.x;           // 256 threads
    h[c] = 0.0f;                   // fp32 h row 0 (d_out)
    reinterpret_cast<uint32_t*>(g_hx)[c] = 0u;   // 256 u32 = 1024B = row 0 of g_hx
}

// ---------------- preamble: 4 embedding projections in one launch -------------
__global__ void gemm_pre(const float* __restrict__ emb,
                         const float* __restrict__ Wz, const float* __restrict__ Wr,
                         const float* __restrict__ Wh, const float* __restrict__ Wo)
{
    const float* Bw; float* C;
    switch (blockIdx.z) {
        case 0:  Bw = Wz; C = g_Ez; break;
        case 1:  Bw = Wr; C = g_Er; break;
        case 2:  Bw = Wh; C = g_Eh; break;
        default: Bw = Wo; C = g_Eo; break;
    }
    __shared__ float As[16][64];
    __shared__ float Bs[16][64];
    const int tid = threadIdx.x;
    const int tx = tid & 15, ty = tid >> 4;
    const int rowBase = blockIdx.y * 64;
    const int colBase = blockIdx.x * 64;
    const int lm  = tid >> 2;
    const int lk  = (tid & 3) * 4;
    const int blk = tid >> 4;
    const int bln = (tid & 15) * 4;
    float acc[4][4] = {};
    for (int kb = 0; kb < 256; kb += 16) {
        int ar = rowBase + lm;
        float4 av = make_float4(0.f, 0.f, 0.f, 0.f);
        if (ar < V_)
            av = *reinterpret_cast<const float4*>(&emb[(size_t)ar * 256 + kb + lk]);
        As[lk + 0][lm] = av.x; As[lk + 1][lm] = av.y;
        As[lk + 2][lm] = av.z; As[lk + 3][lm] = av.w;
        float4 bv = *reinterpret_cast<const float4*>(&Bw[(size_t)(kb + blk) * 256 + colBase + bln]);
        *reinterpret_cast<float4*>(&Bs[blk][bln]) = bv;
        __syncthreads();
#pragma unroll
        for (int k = 0; k < 16; ++k) {
            float4 a4 = *reinterpret_cast<const float4*>(&As[k][ty * 4]);
            float4 b4 = *reinterpret_cast<const float4*>(&Bs[k][tx * 4]);
            float aa[4] = {a4.x, a4.y, a4.z, a4.w};
            float bb[4] = {b4.x, b4.y, b4.z, b4.w};
#pragma unroll
            for (int i = 0; i < 4; ++i)
#pragma unroll
                for (int j = 0; j < 4; ++j)
                    acc[i][j] += aa[i] * bb[j];
        }
        __syncthreads();
    }
#pragma unroll
    for (int i = 0; i < 4; ++i) {
        int r = rowBase + ty * 4 + i;
        if (r < V_)
            *reinterpret_cast<float4*>(&C[(size_t)r * 256 + colBase + tx * 4]) =
                make_float4(acc[i][0], acc[i][1], acc[i][2], acc[i][3]);
    }
}

// ---------------- preamble: 3 weight conversions (single fp16) ----------------
__global__ void conv3(const float* __restrict__ Wz, const float* __restrict__ Wh,
                      const float* __restrict__ Ur)
{
    const float* W; __half* dst;
    switch (blockIdx.y) {
        case 0:  W = Wz + H_ * H_; dst = g_Wzh; break;
        case 1:  W = Wh + H_ * H_; dst = g_Whh; break;
        default: W = Ur;           dst = g_Ur;  break;
    }
    int i = blockIdx.x * 256 + threadIdx.x;
    dst[i] = __float2half_rn(W[i]);
}

// ---------------- per-step gather: one 16B load per neighbor-chunk ------------
__global__ void gather_step(const int*   __restrict__ nei,
                            const int*   __restrict__ xids,
                            const float* __restrict__ bur)
{
    const int msg = blockIdx.x * 4 + (threadIdx.x >> 6);
    const int c4  = threadIdx.x & 63;

    const int xid = xids[msg];
    const float4 bu = reinterpret_cast<const float4*>(bur)[c4];
    const float4 er = reinterpret_cast<const float4*>(&g_Er[(size_t)xid * H_])[c4];
    const float bx = er.x + bu.x, by = er.y + bu.y, bz2 = er.z + bu.z, bw = er.w + bu.w;

    float4 sh = make_float4(0.f, 0.f, 0.f, 0.f);
    float4 sg = make_float4(0.f, 0.f, 0.f, 0.f);
#pragma unroll
    for (int n = 0; n < NB_; ++n) {
        const int j = nei[msg * NB_ + n];
        const uint4 p = g_hx[(size_t)j * 64 + c4];
        const float2 h01 = unpack_h2(p.x);
        const float2 h23 = unpack_h2(p.y);
        const float2 u01 = unpack_h2(p.z);
        const float2 u23 = unpack_h2(p.w);
        sh.x += h01.x; sh.y += h01.y; sh.z += h23.x; sh.w += h23.y;
        sg.x += sigf(bx  + u01.x) * h01.x;
        sg.y += sigf(by  + u01.y) * h01.y;
        sg.z += sigf(bz2 + u23.x) * h23.x;
        sg.w += sigf(bw  + u23.y) * h23.y;
    }
    const size_t o4 = (size_t)msg * 64 + c4;
    {
        __half h0 = __float2half_rn(sh.x), h1 = __float2half_rn(sh.y),
               h2 = __float2half_rn(sh.z), h3 = __float2half_rn(sh.w);
        uint2 u;
        { __half2 a; a.x = h0; a.y = h1; u.x = *reinterpret_cast<uint32_t*>(&a); }
        { __half2 a; a.x = h2; a.y = h3; u.y = *reinterpret_cast<uint32_t*>(&a); }
        reinterpret_cast<uint2*>(g_sh_hi)[o4] = u;
        uint2 v;
        v.x = pack_h2(sh.x - __half2float(h0), sh.y - __half2float(h1));
        v.y = pack_h2(sh.z - __half2float(h2), sh.w - __half2float(h3));
        reinterpret_cast<uint2*>(g_sh_lo)[o4] = v;
    }
    {
        uint2 u;
        u.x = pack_h2(sg.x, sg.y);
        u.y = pack_h2(sg.z, sg.w);
        reinterpret_cast<uint2*>(g_sg)[o4] = u;
    }
}

// ---------------- fused step GEMM: BM=64, BN=256, 512 threads -----------------
// 16 warps = 2(M) x 8(N); warp tile 32x32. Single-term fp16.
// Passes 1+2 fused in ONE k-loop (dual A, dual B).
#define A_STRIDE  40     // 32 + 8 pad (fp16)
#define BW_STRIDE 264    // 256 + 8 pad
#define NH_STRIDE 264

#define ST_A1    0                // 64*40*2  = 5120
#define ST_A2    5120
#define ST_B1    10240            // 32*264*2 = 16896
#define ST_B2    27136
#define ST_SZ    44032            // per stage
#define P_SZ     (2*ST_SZ)        // 88064
#define U_ST_SZ  16896            // pass3 stage (Ur only), double-buffered at base
#define NH_OFF   P_SZ             // 88064, size 64*264*2 = 33792
#define SM_TOTAL (P_SZ + 33792)   // 121856 bytes

// fused dual pass over K=256: acc1 += A1 @ B1, acc2 += A2 @ B2
__device__ __forceinline__ void pass_AB2(
    const __half* __restrict__ A1, const __half* __restrict__ A2,
    const __half* __restrict__ B1, const __half* __restrict__ B2,
    int rowBase, float acc1[2][4][4], float acc2[2][4][4], uint32_t sbase)
{
    const int tid  = threadIdx.x;
    const int lane = tid & 31;
    const int wid  = tid >> 5;
    const int warp_m = wid & 1;
    const int warp_n = wid >> 1;   // 0..7

    const int  asel = tid >> 8;          // 0 or 1
    const int  arow = (tid & 255) >> 2;  // 0..63
    const int  ak   = (tid & 3) * 8;
    const uint32_t a_soff = (asel ? ST_A2 : ST_A1) + (uint32_t)(arow * A_STRIDE + ak) * 2;
    const __half* Ag = asel ? A2 : A1;
    const size_t a_goff = (size_t)(rowBase + arow) * 256 + ak;

    const int brow = tid >> 4;           // 0..31
    const int bcol = (tid & 15) * 8;     // 0..120
    const uint32_t b_soff0 = (uint32_t)(brow * BW_STRIDE + bcol) * 2;
    const uint32_t b_soff1 = (uint32_t)(brow * BW_STRIDE + bcol + 128) * 2;
    const size_t b_goff = (size_t)brow * 256 + bcol;

    cpa16(sbase + a_soff, &Ag[a_goff]);
    cpa16(sbase + ST_B1 + b_soff0, &B1[b_goff]);
    cpa16(sbase + ST_B1 + b_soff1, &B1[b_goff + 128]);
    cpa16(sbase + ST_B2 + b_soff0, &B2[b_goff]);
    cpa16(sbase + ST_B2 + b_soff1, &B2[b_goff + 128]);
    CP_COMMIT();

    for (int it = 0; it < 8; ++it) {
        const uint32_t scur = sbase + (uint32_t)(it & 1) * ST_SZ;
        __syncthreads();
        if (it < 7) {
            const uint32_t snxt = sbase + (uint32_t)((it + 1) & 1) * ST_SZ;
            const int kb = (it + 1) * 32;
            cpa16(snxt + a_soff, &Ag[a_goff + kb]);
            cpa16(snxt + ST_B1 + b_soff0, &B1[b_goff + (size_t)kb * 256]);
            cpa16(snxt + ST_B1 + b_soff1, &B1[b_goff + (size_t)kb * 256 + 128]);
            cpa16(snxt + ST_B2 + b_soff0, &B2[b_goff + (size_t)kb * 256]);
            cpa16(snxt + ST_B2 + b_soff1, &B2[b_goff + (size_t)kb * 256 + 128]);
        }
        CP_COMMIT();
        CP_WAIT1();
        __syncthreads();

#pragma unroll
        for (int ks = 0; ks < 32; ks += 16) {
            uint32_t a1_[2][4], a2_[2][4];
#pragma unroll
            for (int mt = 0; mt < 2; ++mt) {
                const int el = (warp_m * 32 + mt * 16 + (lane & 15)) * A_STRIDE
                             + ks + (lane >> 4) * 8;
                ldsm4(a1_[mt], scur + ST_A1 + el * 2);
                ldsm4(a2_[mt], scur + ST_A2 + el * 2);
            }
#pragma unroll
            for (int np = 0; np < 2; ++np) {
                const int n0 = warp_n * 32 + np * 16;
                const int el = (ks + (lane & 7) + ((lane >> 3) & 1) * 8) * BW_STRIDE
                             + n0 + (lane >> 4) * 8;
                uint32_t b1_[4], b2_[4];
                ldsm4t(b1_, scur + ST_B1 + el * 2);
                ldsm4t(b2_, scur + ST_B2 + el * 2);
#pragma unroll
                for (int mt = 0; mt < 2; ++mt) {
#pragma unroll
                    for (int s = 0; s < 2; ++s) {
                        mma16816(acc1[mt][np * 2 + s], a1_[mt], &b1_[2 * s]);
                        mma16816(acc2[mt][np * 2 + s], a2_[mt], &b2_[2 * s]);
                    }
                }
            }
        }
    }
}

// pass3: acc += new_h(smem fp16) @ Ur(fp16)
__device__ __forceinline__ void pass_U(float acc[2][4][4], uint32_t sbase)
{
    const int tid  = threadIdx.x;
    const int lane = tid & 31;
    const int wid  = tid >> 5;
    const int warp_m = wid & 1;
    const int warp_n = wid >> 1;

    const int brow = tid >> 4;
    const int bcol = (tid & 15) * 8;
    const uint32_t b_soff0 = (uint32_t)(brow * BW_STRIDE + bcol) * 2;
    const uint32_t b_soff1 = (uint32_t)(brow * BW_STRIDE + bcol + 128) * 2;
    const size_t b_goff = (size_t)brow * 256 + bcol;

    cpa16(sbase + b_soff0, &g_Ur[b_goff]);
    cpa16(sbase + b_soff1, &g_Ur[b_goff + 128]);
    CP_COMMIT();

    for (int it = 0; it < 8; ++it) {
        const uint32_t scur = sbase + (uint32_t)(it & 1) * U_ST_SZ;
        __syncthreads();
        if (it < 7) {
            const uint32_t snxt = sbase + (uint32_t)((it + 1) & 1) * U_ST_SZ;
            const int kb = (it + 1) * 32;
            cpa16(snxt + b_soff0, &g_Ur[b_goff + (size_t)kb * 256]);
            cpa16(snxt + b_soff1, &g_Ur[b_goff + (size_t)kb * 256 + 128]);
        }
        CP_COMMIT();
        CP_WAIT1();
        __syncthreads();

        const int kb = it * 32;
#pragma unroll
        for (int ks = 0; ks < 32; ks += 16) {
            uint32_t a_[2][4];
#pragma unroll
            for (int mt = 0; mt < 2; ++mt) {
                const int el = (warp_m * 32 + mt * 16 + (lane & 15)) * NH_STRIDE
                             + kb + ks + (lane >> 4) * 8;
                ldsm4(a_[mt], sbase + NH_OFF + el * 2);
            }
#pragma unroll
            for (int np = 0; np < 2; ++np) {
                const int n0 = warp_n * 32 + np * 16;
                const int el = (ks + (lane & 7) + ((lane >> 3) & 1) * 8) * BW_STRIDE
                             + n0 + (lane >> 4) * 8;
                uint32_t bh_[4];
                ldsm4t(bh_, scur + el * 2);
#pragma unroll
                for (int mt = 0; mt < 2; ++mt) {
#pragma unroll
                    for (int s = 0; s < 2; ++s)
                        mma16816(acc[mt][np * 2 + s], a_[mt], &bh_[2 * s]);
                }
            }
        }
    }
}

__global__ void __launch_bounds__(512, 1) step_mma(
    const float* __restrict__ bz, const float* __restrict__ bhb,
    const int*   __restrict__ xids,
    float* __restrict__ hout, uint32_t* __restrict__ hxout,  // g_hx rows (u32 view)
    int first)
{
    extern __shared__ char dsm[];
    const uint32_t sbase = smem_u32(dsm);
    const int rowBase = blockIdx.x * 64;

    float acc1[2][4][4] = {};
    float acc2[2][4][4] = {};
    if (!first)
        pass_AB2(g_sh_hi, g_sg, g_Wzh, g_Whh, rowBase, acc1, acc2, sbase);

    const int lane = threadIdx.x & 31;
    const int wid  = threadIdx.x >> 5;
    const int warp_m = wid & 1, warp_n = wid >> 1;

    // GRU epilogue -> hout (fp32) + h-half of g_hx + new_h fp16 smem
#pragma unroll
    for (int mt = 0; mt < 2; ++mt) {
#pragma unroll
        for (int nt = 0; nt < 4; ++nt) {
            const int col = warp_n * 32 + nt * 8 + (lane & 3) * 2;
#pragma unroll
            for (int half = 0; half < 2; ++half) {
                const int lr = warp_m * 32 + mt * 16 + (lane >> 2) + half * 8;
                const int r  = rowBase + lr;
                const float a1x = acc1[mt][nt][half * 2 + 0];
                const float a1y = acc1[mt][nt][half * 2 + 1];
                const float a2x = acc2[mt][nt][half * 2 + 0];
                const float a2y = acc2[mt][nt][half * 2 + 1];
                const int xid = xids[r];
                const float2 ez  = *reinterpret_cast<const float2*>(&g_Ez[(size_t)xid * H_ + col]);
                const float2 eh  = *reinterpret_cast<const float2*>(&g_Eh[(size_t)xid * H_ + col]);
                const float2 bzv = *reinterpret_cast<const float2*>(&bz[col]);
                const float2 bhv = *reinterpret_cast<const float2*>(&bhb[col]);
                float sh0 = 0.f, sh1 = 0.f;
                if (!first) {
                    const uint32_t shh = *reinterpret_cast<const uint32_t*>(&g_sh_hi[(size_t)r * H_ + col]);
                    const uint32_t shl = *reinterpret_cast<const uint32_t*>(&g_sh_lo[(size_t)r * H_ + col]);
                    const float2 sh_h = unpack_h2(shh);
                    const float2 sh_l = unpack_h2(shl);
                    sh0 = sh_h.x + sh_l.x;
                    sh1 = sh_h.y + sh_l.y;
                }
                const float z0 = sigf(ez.x + bzv.x + a1x);
                const float z1 = sigf(ez.y + bzv.y + a1y);
                const float p0 = tanha(eh.x + bhv.x + a2x);
                const float p1 = tanha(eh.y + bhv.y + a2y);
                const float o0 = (1.0f - z0) * sh0 + z0 * p0;
                const float o1 = (1.0f - z1) * sh1 + z1 * p1;
                *reinterpret_cast<float2*>(&hout[(size_t)r * H_ + col]) = make_float2(o0, o1);
                const uint32_t soff = (uint32_t)(lr * NH_STRIDE + col) * 2;
                const uint32_t hp = pack_h2(o0, o1);
                *reinterpret_cast<uint32_t*>(dsm + NH_OFF + soff) = hp;
                // h-half of interleaved 16B chunk: word = (r*64 + col/4)*4 + ((col>>1)&1)
                hxout[((size_t)r * 64 + (col >> 2)) * 4 + ((col >> 1) & 1)] = hp;
            }
        }
    }

    // pass3: hU = new_h @ Ur (A from smem); store into u-half of g_hx
    float acc3[2][4][4] = {};
    pass_U(acc3, sbase);

#pragma unroll
    for (int mt = 0; mt < 2; ++mt) {
#pragma unroll
        for (int nt = 0; nt < 4; ++nt) {
            const int col = warp_n * 32 + nt * 8 + (lane & 3) * 2;
            const int r0  = rowBase + warp_m * 32 + mt * 16 + (lane >> 2);
            const uint32_t sub = (uint32_t)(col >> 2) * 4 + 2 + ((col >> 1) & 1);
            hxout[(size_t)r0 * 256 + sub] =
                pack_h2(acc3[mt][nt][0], acc3[mt][nt][1]);
            hxout[(size_t)(r0 + 8) * 256 + sub] =
                pack_h2(acc3[mt][nt][2], acc3[mt][nt][3]);
        }
    }
}

// ---------------- fused root aggregate ----------------------------------------
__global__ void root_fused(const float* __restrict__ h, const int* __restrict__ rnei,
                           const int* __restrict__ rwid, const float* __restrict__ Woh,
                           const float* __restrict__ bo, float* __restrict__ out)
{
    __shared__ float s_sum[256];
    __shared__ int sj[NB_];
    const int b = blockIdx.x;
    const int c = threadIdx.x;
    if (c < NB_) sj[c] = rnei[b * NB_ + c];
    __syncthreads();
    float s = 0.f;
#pragma unroll
    for (int n = 0; n < NB_; ++n)
        s += h[(size_t)sj[n] * 256 + c];
    s_sum[c] = s;
    __syncthreads();
    float acc = 0.f;
#pragma unroll 8
    for (int k = 0; k < 256; ++k)
        acc += s_sum[k] * Woh[(size_t)k * 256 + c];
    const int xid = rwid[b];
    float v = g_Eo[(size_t)xid * 256 + c] + bo[c] + acc;
    out[(size_t)b * 256 + c] = fmaxf(v, 0.0f);
}

// ---------------- launch ------------------------------------------------------
extern "C" void kernel_launch(void* const* d_in, const int* in_sizes, int n_in,
                              void* d_out, int out_size)
{
    const int*   x_ids    = (const int*)  d_in[0];
    const int*   nei_idx  = (const int*)  d_in[1];
    const int*   root_wid = (const int*)  d_in[2];
    const int*   root_nei = (const int*)  d_in[3];
    const float* emb      = (const float*)d_in[4];
    const float* Wz       = (const float*)d_in[5];
    const float* bz       = (const float*)d_in[6];
    const float* Wr       = (const float*)d_in[7];
    const float* Ur       = (const float*)d_in[8];
    const float* bur      = (const float*)d_in[9];
    const float* Wh       = (const float*)d_in[10];
    const float* bh       = (const float*)d_in[11];
    const float* Wo       = (const float*)d_in[12];
    const float* bo       = (const float*)d_in[13];

    float* out  = (float*)d_out;
    float* h    = out;
    float* rvec = out + (size_t)(M_ + 1) * H_;

    uint4* p_hx;
    cudaGetSymbolAddress((void**)&p_hx, g_hx);

    cudaFuncSetAttribute(step_mma, cudaFuncAttributeMaxDynamicSharedMemorySize, SM_TOTAL);

    init_zero<<<1, 256>>>(h);

    dim3 gpre(4, (V_ + 63) / 64, 4);
    gemm_pre<<<gpre, 256>>>(emb, Wz, Wr, Wh, Wo);
    conv3<<<dim3(256, 3), 256>>>(Wz, Wh, Ur);

    for (int t = 0; t < T_; ++t) {
        if (t > 0)
            gather_step<<<E_ / 4, 256>>>(nei_idx + (size_t)t * E_ * NB_,
                                         x_ids + (size_t)t * E_, bur);
        step_mma<<<E_ / 64, 512, SM_TOTAL>>>(
            bz, bh, x_ids + (size_t)t * E_,
            h + (size_t)(1 + t * E_) * H_,
            reinterpret_cast<uint32_t*>(p_hx + (size_t)(1 + t * E_) * 64),
            (t == 0) ? 1 : 0);
    }

    root_fused<<<B_, 256>>>(h, root_nei, root_wid, Wo + (size_t)H_ * H_, bo, rvec);
}

// round 16
// speedup vs baseline: 1.0004x; 1.0004x over previous
#include <cuda_runtime.h>
#include <cuda_fp16.h>
#include <math.h>
#include <stdint.h>

#define T_  12
#define E_  8192
#define H_  256
#define V_  800
#define B_  256
#define NB_ 8
#define M_  (T_*E_)   // 98304 messages; h has 1+M rows (row 0 = pad)

// ---------------- scratch (static device arrays; no allocs allowed) ----------
// interleaved fp16 h + hU: per row, 64 chunks of 16B = {h2(c0c1), h2(c2c3), u2(c0c1), u2(c2c3)}
__device__ uint4 g_hx[(size_t)(M_+1)*64];
__device__ float g_Ez[(size_t)V_*H_];
__device__ float g_Er[(size_t)V_*H_];
__device__ float g_Eh[(size_t)V_*H_];
__device__ float g_Eo[(size_t)V_*H_];

// fp16 operands (single-term weights; sum_h keeps hi+lo for the epilogue path)
__device__ __half g_sh_hi[(size_t)E_*H_], g_sh_lo[(size_t)E_*H_];
__device__ __half g_sg   [(size_t)E_*H_];
__device__ __half g_Wzh[H_*H_];
__device__ __half g_Whh[H_*H_];
__device__ __half g_Ur [H_*H_];

// hardware tanh (sm_75+): ~2^-11 max rel error
__device__ __forceinline__ float tanha(float x) {
    float t;
    asm("tanh.approx.f32 %0, %1;" : "=f"(t) : "f"(x));
    return t;
}
// sigmoid via tanh: sigma(x) = 0.5*tanh(x/2) + 0.5  (1 MUFU)
__device__ __forceinline__ float sigf(float x) {
    return fmaf(0.5f, tanha(0.5f * x), 0.5f);
}

// ---------------- PTX helpers -------------------------------------------------
__device__ __forceinline__ uint32_t smem_u32(const void* p) {
    return (uint32_t)__cvta_generic_to_shared(p);
}
__device__ __forceinline__ void ldsm4(uint32_t* r, uint32_t a) {
    asm volatile("ldmatrix.sync.aligned.m8n8.x4.shared.b16 {%0,%1,%2,%3},[%4];\n"
                 : "=r"(r[0]), "=r"(r[1]), "=r"(r[2]), "=r"(r[3]) : "r"(a));
}
__device__ __forceinline__ void ldsm4t(uint32_t* r, uint32_t a) {
    asm volatile("ldmatrix.sync.aligned.m8n8.x4.trans.shared.b16 {%0,%1,%2,%3},[%4];\n"
                 : "=r"(r[0]), "=r"(r[1]), "=r"(r[2]), "=r"(r[3]) : "r"(a));
}
__device__ __forceinline__ void mma16816(float* d, const uint32_t* a, const uint32_t* b) {
    asm volatile("mma.sync.aligned.m16n8k16.row.col.f32.f16.f16.f32 "
                 "{%0,%1,%2,%3},{%4,%5,%6,%7},{%8,%9},{%0,%1,%2,%3};\n"
                 : "+f"(d[0]), "+f"(d[1]), "+f"(d[2]), "+f"(d[3])
                 : "r"(a[0]), "r"(a[1]), "r"(a[2]), "r"(a[3]), "r"(b[0]), "r"(b[1]));
}
__device__ __forceinline__ void cpa16(uint32_t dst, const void* src) {
    asm volatile("cp.async.cg.shared.global [%0],[%1],16;\n" :: "r"(dst), "l"(src));
}
#define CP_COMMIT()  asm volatile("cp.async.commit_group;\n" ::: "memory")
#define CP_WAIT1()   asm volatile("cp.async.wait_group 1;\n" ::: "memory")

// streaming (evict-first) fp32x2 store: keeps the write-only h stream out of L2
__device__ __forceinline__ void stg_cs_f2(float* p, float a, float b) {
    asm volatile("st.global.cs.v2.f32 [%0],{%1,%2};\n" :: "l"(p), "f"(a), "f"(b) : "memory");
}

__device__ __forceinline__ uint32_t pack_h2(float a, float b) {
    __half2 t; t.x = __float2half_rn(a); t.y = __float2half_rn(b);
    return *reinterpret_cast<uint32_t*>(&t);
}
__device__ __forceinline__ float2 unpack_h2(uint32_t u) {
    __half2 t = *reinterpret_cast<__half2*>(&u);
    return make_float2(__half2float(t.x), __half2float(t.y));
}

// ---------------- init --------------------------------------------------------
__global__ void init_zero(float* __restrict__ h)
{
    int c = threadIdx.x;           // 256 threads
    h[c] = 0.0f;                   // fp32 h row 0 (d_out)
    reinterpret_cast<uint32_t*>(g_hx)[c] = 0u;   // 256 u32 = 1024B = row 0 of g_hx
}

// ---------------- preamble: 4 embedding projections in one launch -------------
__global__ void gemm_pre(const float* __restrict__ emb,
                         const float* __restrict__ Wz, const float* __restrict__ Wr,
                         const float* __restrict__ Wh, const float* __restrict__ Wo)
{
    const float* Bw; float* C;
    switch (blockIdx.z) {
        case 0:  Bw = Wz; C = g_Ez; break;
        case 1:  Bw = Wr; C = g_Er; break;
        case 2:  Bw = Wh; C = g_Eh; break;
        default: Bw = Wo; C = g_Eo; break;
    }
    __shared__ float As[16][64];
    __shared__ float Bs[16][64];
    const int tid = threadIdx.x;
    const int tx = tid & 15, ty = tid >> 4;
    const int rowBase = blockIdx.y * 64;
    const int colBase = blockIdx.x * 64;
    const int lm  = tid >> 2;
    const int lk  = (tid & 3) * 4;
    const int blk = tid >> 4;
    const int bln = (tid & 15) * 4;
    float acc[4][4] = {};
    for (int kb = 0; kb < 256; kb += 16) {
        int ar = rowBase + lm;
        float4 av = make_float4(0.f, 0.f, 0.f, 0.f);
        if (ar < V_)
            av = *reinterpret_cast<const float4*>(&emb[(size_t)ar * 256 + kb + lk]);
        As[lk + 0][lm] = av.x; As[lk + 1][lm] = av.y;
        As[lk + 2][lm] = av.z; As[lk + 3][lm] = av.w;
        float4 bv = *reinterpret_cast<const float4*>(&Bw[(size_t)(kb + blk) * 256 + colBase + bln]);
        *reinterpret_cast<float4*>(&Bs[blk][bln]) = bv;
        __syncthreads();
#pragma unroll
        for (int k = 0; k < 16; ++k) {
            float4 a4 = *reinterpret_cast<const float4*>(&As[k][ty * 4]);
            float4 b4 = *reinterpret_cast<const float4*>(&Bs[k][tx * 4]);
            float aa[4] = {a4.x, a4.y, a4.z, a4.w};
            float bb[4] = {b4.x, b4.y, b4.z, b4.w};
#pragma unroll
            for (int i = 0; i < 4; ++i)
#pragma unroll
                for (int j = 0; j < 4; ++j)
                    acc[i][j] += aa[i] * bb[j];
        }
        __syncthreads();
    }
#pragma unroll
    for (int i = 0; i < 4; ++i) {
        int r = rowBase + ty * 4 + i;
        if (r < V_)
            *reinterpret_cast<float4*>(&C[(size_t)r * 256 + colBase + tx * 4]) =
                make_float4(acc[i][0], acc[i][1], acc[i][2], acc[i][3]);
    }
}

// ---------------- preamble: 3 weight conversions (single fp16) ----------------
__global__ void conv3(const float* __restrict__ Wz, const float* __restrict__ Wh,
                      const float* __restrict__ Ur)
{
    const float* W; __half* dst;
    switch (blockIdx.y) {
        case 0:  W = Wz + H_ * H_; dst = g_Wzh; break;
        case 1:  W = Wh + H_ * H_; dst = g_Whh; break;
        default: W = Ur;           dst = g_Ur;  break;
    }
    int i = blockIdx.x * 256 + threadIdx.x;
    dst[i] = __float2half_rn(W[i]);
}

// ---------------- per-step gather: one 16B load per neighbor-chunk ------------
__global__ void gather_step(const int*   __restrict__ nei,
                            const int*   __restrict__ xids,
                            const float* __restrict__ bur)
{
    const int msg = blockIdx.x * 4 + (threadIdx.x >> 6);
    const int c4  = threadIdx.x & 63;

    const int xid = xids[msg];
    const float4 bu = reinterpret_cast<const float4*>(bur)[c4];
    const float4 er = reinterpret_cast<const float4*>(&g_Er[(size_t)xid * H_])[c4];
    const float bx = er.x + bu.x, by = er.y + bu.y, bz2 = er.z + bu.z, bw = er.w + bu.w;

    float4 sh = make_float4(0.f, 0.f, 0.f, 0.f);
    float4 sg = make_float4(0.f, 0.f, 0.f, 0.f);
#pragma unroll
    for (int n = 0; n < NB_; ++n) {
        const int j = nei[msg * NB_ + n];
        const uint4 p = g_hx[(size_t)j * 64 + c4];
        const float2 h01 = unpack_h2(p.x);
        const float2 h23 = unpack_h2(p.y);
        const float2 u01 = unpack_h2(p.z);
        const float2 u23 = unpack_h2(p.w);
        sh.x += h01.x; sh.y += h01.y; sh.z += h23.x; sh.w += h23.y;
        sg.x += sigf(bx  + u01.x) * h01.x;
        sg.y += sigf(by  + u01.y) * h01.y;
        sg.z += sigf(bz2 + u23.x) * h23.x;
        sg.w += sigf(bw  + u23.y) * h23.y;
    }
    const size_t o4 = (size_t)msg * 64 + c4;
    {
        __half h0 = __float2half_rn(sh.x), h1 = __float2half_rn(sh.y),
               h2 = __float2half_rn(sh.z), h3 = __float2half_rn(sh.w);
        uint2 u;
        { __half2 a; a.x = h0; a.y = h1; u.x = *reinterpret_cast<uint32_t*>(&a); }
        { __half2 a; a.x = h2; a.y = h3; u.y = *reinterpret_cast<uint32_t*>(&a); }
        reinterpret_cast<uint2*>(g_sh_hi)[o4] = u;
        uint2 v;
        v.x = pack_h2(sh.x - __half2float(h0), sh.y - __half2float(h1));
        v.y = pack_h2(sh.z - __half2float(h2), sh.w - __half2float(h3));
        reinterpret_cast<uint2*>(g_sh_lo)[o4] = v;
    }
    {
        uint2 u;
        u.x = pack_h2(sg.x, sg.y);
        u.y = pack_h2(sg.z, sg.w);
        reinterpret_cast<uint2*>(g_sg)[o4] = u;
    }
}

// ---------------- fused step GEMM: BM=64, BN=256, 512 threads -----------------
// 16 warps = 2(M) x 8(N); warp tile 32x32. Single-term fp16.
// Passes 1+2 fused in ONE k-loop (dual A, dual B).
#define A_STRIDE  40     // 32 + 8 pad (fp16)
#define BW_STRIDE 264    // 256 + 8 pad
#define NH_STRIDE 264

#define ST_A1    0                // 64*40*2  = 5120
#define ST_A2    5120
#define ST_B1    10240            // 32*264*2 = 16896
#define ST_B2    27136
#define ST_SZ    44032            // per stage
#define P_SZ     (2*ST_SZ)        // 88064
#define U_ST_SZ  16896            // pass3 stage (Ur only), double-buffered at base
#define NH_OFF   P_SZ             // 88064, size 64*264*2 = 33792
#define SM_TOTAL (P_SZ + 33792)   // 121856 bytes

// fused dual pass over K=256: acc1 += A1 @ B1, acc2 += A2 @ B2
__device__ __forceinline__ void pass_AB2(
    const __half* __restrict__ A1, const __half* __restrict__ A2,
    const __half* __restrict__ B1, const __half* __restrict__ B2,
    int rowBase, float acc1[2][4][4], float acc2[2][4][4], uint32_t sbase)
{
    const int tid  = threadIdx.x;
    const int lane = tid & 31;
    const int wid  = tid >> 5;
    const int warp_m = wid & 1;
    const int warp_n = wid >> 1;   // 0..7

    const int  asel = tid >> 8;          // 0 or 1
    const int  arow = (tid & 255) >> 2;  // 0..63
    const int  ak   = (tid & 3) * 8;
    const uint32_t a_soff = (asel ? ST_A2 : ST_A1) + (uint32_t)(arow * A_STRIDE + ak) * 2;
    const __half* Ag = asel ? A2 : A1;
    const size_t a_goff = (size_t)(rowBase + arow) * 256 + ak;

    const int brow = tid >> 4;           // 0..31
    const int bcol = (tid & 15) * 8;     // 0..120
    const uint32_t b_soff0 = (uint32_t)(brow * BW_STRIDE + bcol) * 2;
    const uint32_t b_soff1 = (uint32_t)(brow * BW_STRIDE + bcol + 128) * 2;
    const size_t b_goff = (size_t)brow * 256 + bcol;

    cpa16(sbase + a_soff, &Ag[a_goff]);
    cpa16(sbase + ST_B1 + b_soff0, &B1[b_goff]);
    cpa16(sbase + ST_B1 + b_soff1, &B1[b_goff + 128]);
    cpa16(sbase + ST_B2 + b_soff0, &B2[b_goff]);
    cpa16(sbase + ST_B2 + b_soff1, &B2[b_goff + 128]);
    CP_COMMIT();

    for (int it = 0; it < 8; ++it) {
        const uint32_t scur = sbase + (uint32_t)(it & 1) * ST_SZ;
        __syncthreads();
        if (it < 7) {
            const uint32_t snxt = sbase + (uint32_t)((it + 1) & 1) * ST_SZ;
            const int kb = (it + 1) * 32;
            cpa16(snxt + a_soff, &Ag[a_goff + kb]);
            cpa16(snxt + ST_B1 + b_soff0, &B1[b_goff + (size_t)kb * 256]);
            cpa16(snxt + ST_B1 + b_soff1, &B1[b_goff + (size_t)kb * 256 + 128]);
            cpa16(snxt + ST_B2 + b_soff0, &B2[b_goff + (size_t)kb * 256]);
            cpa16(snxt + ST_B2 + b_soff1, &B2[b_goff + (size_t)kb * 256 + 128]);
        }
        CP_COMMIT();
        CP_WAIT1();
        __syncthreads();

#pragma unroll
        for (int ks = 0; ks < 32; ks += 16) {
            uint32_t a1_[2][4], a2_[2][4];
#pragma unroll
            for (int mt = 0; mt < 2; ++mt) {
                const int el = (warp_m * 32 + mt * 16 + (lane & 15)) * A_STRIDE
                             + ks + (lane >> 4) * 8;
                ldsm4(a1_[mt], scur + ST_A1 + el * 2);
                ldsm4(a2_[mt], scur + ST_A2 + el * 2);
            }
#pragma unroll
            for (int np = 0; np < 2; ++np) {
                const int n0 = warp_n * 32 + np * 16;
                const int el = (ks + (lane & 7) + ((lane >> 3) & 1) * 8) * BW_STRIDE
                             + n0 + (lane >> 4) * 8;
                uint32_t b1_[4], b2_[4];
                ldsm4t(b1_, scur + ST_B1 + el * 2);
                ldsm4t(b2_, scur + ST_B2 + el * 2);
#pragma unroll
                for (int mt = 0; mt < 2; ++mt) {
#pragma unroll
                    for (int s = 0; s < 2; ++s) {
                        mma16816(acc1[mt][np * 2 + s], a1_[mt], &b1_[2 * s]);
                        mma16816(acc2[mt][np * 2 + s], a2_[mt], &b2_[2 * s]);
                    }
                }
            }
        }
    }
}

// pass3: acc += new_h(smem fp16) @ Ur(fp16)
__device__ __forceinline__ void pass_U(float acc[2][4][4], uint32_t sbase)
{
    const int tid  = threadIdx.x;
    const int lane = tid & 31;
    const int wid  = tid >> 5;
    const int warp_m = wid & 1;
    const int warp_n = wid >> 1;

    const int brow = tid >> 4;
    const int bcol = (tid & 15) * 8;
    const uint32_t b_soff0 = (uint32_t)(brow * BW_STRIDE + bcol) * 2;
    const uint32_t b_soff1 = (uint32_t)(brow * BW_STRIDE + bcol + 128) * 2;
    const size_t b_goff = (size_t)brow * 256 + bcol;

    cpa16(sbase + b_soff0, &g_Ur[b_goff]);
    cpa16(sbase + b_soff1, &g_Ur[b_goff + 128]);
    CP_COMMIT();

    for (int it = 0; it < 8; ++it) {
        const uint32_t scur = sbase + (uint32_t)(it & 1) * U_ST_SZ;
        __syncthreads();
        if (it < 7) {
            const uint32_t snxt = sbase + (uint32_t)((it + 1) & 1) * U_ST_SZ;
            const int kb = (it + 1) * 32;
            cpa16(snxt + b_soff0, &g_Ur[b_goff + (size_t)kb * 256]);
            cpa16(snxt + b_soff1, &g_Ur[b_goff + (size_t)kb * 256 + 128]);
        }
        CP_COMMIT();
        CP_WAIT1();
        __syncthreads();

        const int kb = it * 32;
#pragma unroll
        for (int ks = 0; ks < 32; ks += 16) {
            uint32_t a_[2][4];
#pragma unroll
            for (int mt = 0; mt < 2; ++mt) {
                const int el = (warp_m * 32 + mt * 16 + (lane & 15)) * NH_STRIDE
                             + kb + ks + (lane >> 4) * 8;
                ldsm4(a_[mt], sbase + NH_OFF + el * 2);
            }
#pragma unroll
            for (int np = 0; np < 2; ++np) {
                const int n0 = warp_n * 32 + np * 16;
                const int el = (ks + (lane & 7) + ((lane >> 3) & 1) * 8) * BW_STRIDE
                             + n0 + (lane >> 4) * 8;
                uint32_t bh_[4];
                ldsm4t(bh_, scur + el * 2);
#pragma unroll
                for (int mt = 0; mt < 2; ++mt) {
#pragma unroll
                    for (int s = 0; s < 2; ++s)
                        mma16816(acc[mt][np * 2 + s], a_[mt], &bh_[2 * s]);
                }
            }
        }
    }
}

__global__ void __launch_bounds__(512, 1) step_mma(
    const float* __restrict__ bz, const float* __restrict__ bhb,
    const int*   __restrict__ xids,
    float* __restrict__ hout, uint32_t* __restrict__ hxout,  // g_hx rows (u32 view)
    int first)
{
    extern __shared__ char dsm[];
    const uint32_t sbase = smem_u32(dsm);
    const int rowBase = blockIdx.x * 64;

    float acc1[2][4][4] = {};
    float acc2[2][4][4] = {};
    if (!first)
        pass_AB2(g_sh_hi, g_sg, g_Wzh, g_Whh, rowBase, acc1, acc2, sbase);

    const int lane = threadIdx.x & 31;
    const int wid  = threadIdx.x >> 5;
    const int warp_m = wid & 1, warp_n = wid >> 1;

    // GRU epilogue -> hout (fp32, STREAMING store) + h-half of g_hx + new_h fp16 smem
#pragma unroll
    for (int mt = 0; mt < 2; ++mt) {
#pragma unroll
        for (int nt = 0; nt < 4; ++nt) {
            const int col = warp_n * 32 + nt * 8 + (lane & 3) * 2;
#pragma unroll
            for (int half = 0; half < 2; ++half) {
                const int lr = warp_m * 32 + mt * 16 + (lane >> 2) + half * 8;
                const int r  = rowBase + lr;
                const float a1x = acc1[mt][nt][half * 2 + 0];
                const float a1y = acc1[mt][nt][half * 2 + 1];
                const float a2x = acc2[mt][nt][half * 2 + 0];
                const float a2y = acc2[mt][nt][half * 2 + 1];
                const int xid = xids[r];
                const float2 ez  = *reinterpret_cast<const float2*>(&g_Ez[(size_t)xid * H_ + col]);
                const float2 eh  = *reinterpret_cast<const float2*>(&g_Eh[(size_t)xid * H_ + col]);
                const float2 bzv = *reinterpret_cast<const float2*>(&bz[col]);
                const float2 bhv = *reinterpret_cast<const float2*>(&bhb[col]);
                float sh0 = 0.f, sh1 = 0.f;
                if (!first) {
                    const uint32_t shh = *reinterpret_cast<const uint32_t*>(&g_sh_hi[(size_t)r * H_ + col]);
                    const uint32_t shl = *reinterpret_cast<const uint32_t*>(&g_sh_lo[(size_t)r * H_ + col]);
                    const float2 sh_h = unpack_h2(shh);
                    const float2 sh_l = unpack_h2(shl);
                    sh0 = sh_h.x + sh_l.x;
                    sh1 = sh_h.y + sh_l.y;
                }
                const float z0 = sigf(ez.x + bzv.x + a1x);
                const float z1 = sigf(ez.y + bzv.y + a1y);
                const float p0 = tanha(eh.x + bhv.x + a2x);
                const float p1 = tanha(eh.y + bhv.y + a2y);
                const float o0 = (1.0f - z0) * sh0 + z0 * p0;
                const float o1 = (1.0f - z1) * sh1 + z1 * p1;
                stg_cs_f2(&hout[(size_t)r * H_ + col], o0, o1);
                const uint32_t soff = (uint32_t)(lr * NH_STRIDE + col) * 2;
                const uint32_t hp = pack_h2(o0, o1);
                *reinterpret_cast<uint32_t*>(dsm + NH_OFF + soff) = hp;
                // h-half of interleaved 16B chunk: word = (r*64 + col/4)*4 + ((col>>1)&1)
                hxout[((size_t)r * 64 + (col >> 2)) * 4 + ((col >> 1) & 1)] = hp;
            }
        }
    }

    // pass3: hU = new_h @ Ur (A from smem); store into u-half of g_hx
    float acc3[2][4][4] = {};
    pass_U(acc3, sbase);

#pragma unroll
    for (int mt = 0; mt < 2; ++mt) {
#pragma unroll
        for (int nt = 0; nt < 4; ++nt) {
            const int col = warp_n * 32 + nt * 8 + (lane & 3) * 2;
            const int r0  = rowBase + warp_m * 32 + mt * 16 + (lane >> 2);
            const uint32_t sub = (uint32_t)(col >> 2) * 4 + 2 + ((col >> 1) & 1);
            hxout[(size_t)r0 * 256 + sub] =
                pack_h2(acc3[mt][nt][0], acc3[mt][nt][1]);
            hxout[(size_t)(r0 + 8) * 256 + sub] =
                pack_h2(acc3[mt][nt][2], acc3[mt][nt][3]);
        }
    }
}

// ---------------- fused root aggregate ----------------------------------------
__global__ void root_fused(const float* __restrict__ h, const int* __restrict__ rnei,
                           const int* __restrict__ rwid, const float* __restrict__ Woh,
                           const float* __restrict__ bo, float* __restrict__ out)
{
    __shared__ float s_sum[256];
    __shared__ int sj[NB_];
    const int b = blockIdx.x;
    const int c = threadIdx.x;
    if (c < NB_) sj[c] = rnei[b * NB_ + c];
    __syncthreads();
    float s = 0.f;
#pragma unroll
    for (int n = 0; n < NB_; ++n)
        s += h[(size_t)sj[n] * 256 + c];
    s_sum[c] = s;
    __syncthreads();
    float acc = 0.f;
#pragma unroll 8
    for (int k = 0; k < 256; ++k)
        acc += s_sum[k] * Woh[(size_t)k * 256 + c];
    const int xid = rwid[b];
    float v = g_Eo[(size_t)xid * 256 + c] + bo[c] + acc;
    out[(size_t)b * 256 + c] = fmaxf(v, 0.0f);
}

// ---------------- launch ------------------------------------------------------
extern "C" void kernel_launch(void* const* d_in, const int* in_sizes, int n_in,
                              void* d_out, int out_size)
{
    const int*   x_ids    = (const int*)  d_in[0];
    const int*   nei_idx  = (const int*)  d_in[1];
    const int*   root_wid = (const int*)  d_in[2];
    const int*   root_nei = (const int*)  d_in[3];
    const float* emb      = (const float*)d_in[4];
    const float* Wz       = (const float*)d_in[5];
    const float* bz       = (const float*)d_in[6];
    const float* Wr       = (const float*)d_in[7];
    const float* Ur       = (const float*)d_in[8];
    const float* bur      = (const float*)d_in[9];
    const float* Wh       = (const float*)d_in[10];
    const float* bh       = (const float*)d_in[11];
    const float* Wo       = (const float*)d_in[12];
    const float* bo       = (const float*)d_in[13];

    float* out  = (float*)d_out;
    float* h    = out;
    float* rvec = out + (size_t)(M_ + 1) * H_;

    uint4* p_hx;
    cudaGetSymbolAddress((void**)&p_hx, g_hx);

    cudaFuncSetAttribute(step_mma, cudaFuncAttributeMaxDynamicSharedMemorySize, SM_TOTAL);

    init_zero<<<1, 256>>>(h);

    dim3 gpre(4, (V_ + 63) / 64, 4);
    gemm_pre<<<gpre, 256>>>(emb, Wz, Wr, Wh, Wo);
    conv3<<<dim3(256, 3), 256>>>(Wz, Wh, Ur);

    for (int t = 0; t < T_; ++t) {
        if (t > 0)
            gather_step<<<E_ / 4, 256>>>(nei_idx + (size_t)t * E_ * NB_,
                                         x_ids + (size_t)t * E_, bur);
        step_mma<<<E_ / 64, 512, SM_TOTAL>>>(
            bz, bh, x_ids + (size_t)t * E_,
            h + (size_t)(1 + t * E_) * H_,
            reinterpret_cast<uint32_t*>(p_hx + (size_t)(1 + t * E_) * 64),
            (t == 0) ? 1 : 0);
    }

    root_fused<<<B_, 256>>>(h, root_nei, root_wid, Wo + (size_t)H_ * H_, bo, rvec);
}

// round 17
// speedup vs baseline: 1.0416x; 1.0412x over previous
#include <cuda_runtime.h>
#include <cuda_fp16.h>
#include <math.h>
#include <stdint.h>

#define T_  12
#define E_  8192
#define H_  256
#define V_  800
#define B_  256
#define NB_ 8
#define M_  (T_*E_)   // 98304 messages; h has 1+M rows (row 0 = pad)

// ---------------- scratch (static device arrays; no allocs allowed) ----------
__device__ __half g_hU16[(size_t)(M_+1)*H_];   // h @ Ur, fp16 (sigmoid arg only)
__device__ float g_Ez[(size_t)V_*H_];
__device__ float g_Er[(size_t)V_*H_];
__device__ float g_Eh[(size_t)V_*H_];
__device__ float g_Eo[(size_t)V_*H_];

// fp16 operands (single-term weights; sum_h keeps hi+lo for the epilogue path)
__device__ __half g_sh_hi[(size_t)E_*H_], g_sh_lo[(size_t)E_*H_];
__device__ __half g_sg   [(size_t)E_*H_];
__device__ __half g_Wzh[H_*H_];
__device__ __half g_Whh[H_*H_];
__device__ __half g_Ur [H_*H_];

// hardware tanh (sm_75+): ~2^-11 max rel error
__device__ __forceinline__ float tanha(float x) {
    float t;
    asm("tanh.approx.f32 %0, %1;" : "=f"(t) : "f"(x));
    return t;
}
// sigmoid via tanh: sigma(x) = 0.5*tanh(x/2) + 0.5  (1 MUFU)
__device__ __forceinline__ float sigf(float x) {
    return fmaf(0.5f, tanha(0.5f * x), 0.5f);
}

__device__ __forceinline__ void grid_dep_sync() {
#if __CUDA_ARCH__ >= 900
    cudaGridDependencySynchronize();
#endif
}

// ---------------- PTX helpers -------------------------------------------------
__device__ __forceinline__ uint32_t smem_u32(const void* p) {
    return (uint32_t)__cvta_generic_to_shared(p);
}
__device__ __forceinline__ void ldsm4(uint32_t* r, uint32_t a) {
    asm volatile("ldmatrix.sync.aligned.m8n8.x4.shared.b16 {%0,%1,%2,%3},[%4];\n"
                 : "=r"(r[0]), "=r"(r[1]), "=r"(r[2]), "=r"(r[3]) : "r"(a));
}
__device__ __forceinline__ void ldsm4t(uint32_t* r, uint32_t a) {
    asm volatile("ldmatrix.sync.aligned.m8n8.x4.trans.shared.b16 {%0,%1,%2,%3},[%4];\n"
                 : "=r"(r[0]), "=r"(r[1]), "=r"(r[2]), "=r"(r[3]) : "r"(a));
}
__device__ __forceinline__ void mma16816(float* d, const uint32_t* a, const uint32_t* b) {
    asm volatile("mma.sync.aligned.m16n8k16.row.col.f32.f16.f16.f32 "
                 "{%0,%1,%2,%3},{%4,%5,%6,%7},{%8,%9},{%0,%1,%2,%3};\n"
                 : "+f"(d[0]), "+f"(d[1]), "+f"(d[2]), "+f"(d[3])
                 : "r"(a[0]), "r"(a[1]), "r"(a[2]), "r"(a[3]), "r"(b[0]), "r"(b[1]));
}
__device__ __forceinline__ void cpa16(uint32_t dst, const void* src) {
    asm volatile("cp.async.cg.shared.global [%0],[%1],16;\n" :: "r"(dst), "l"(src));
}
#define CP_COMMIT()  asm volatile("cp.async.commit_group;\n" ::: "memory")
#define CP_WAIT1()   asm volatile("cp.async.wait_group 1;\n" ::: "memory")

__device__ __forceinline__ uint32_t pack_h2(float a, float b) {
    __half2 t; t.x = __float2half_rn(a); t.y = __float2half_rn(b);
    return *reinterpret_cast<uint32_t*>(&t);
}
__device__ __forceinline__ float2 unpack_h2(uint32_t u) {
    __half2 t = *reinterpret_cast<__half2*>(&u);
    return make_float2(__half2float(t.x), __half2float(t.y));
}

// ---------------- init --------------------------------------------------------
__global__ void init_zero(float* __restrict__ h)
{
    int c = threadIdx.x;
    h[c]      = 0.0f;
    g_hU16[c] = __float2half_rn(0.0f);
}

// ---------------- preamble: 4 embedding projections in one launch -------------
__global__ void gemm_pre(const float* __restrict__ emb,
                         const float* __restrict__ Wz, const float* __restrict__ Wr,
                         const float* __restrict__ Wh, const float* __restrict__ Wo)
{
    const float* Bw; float* C;
    switch (blockIdx.z) {
        case 0:  Bw = Wz; C = g_Ez; break;
        case 1:  Bw = Wr; C = g_Er; break;
        case 2:  Bw = Wh; C = g_Eh; break;
        default: Bw = Wo; C = g_Eo; break;
    }
    __shared__ float As[16][64];
    __shared__ float Bs[16][64];
    const int tid = threadIdx.x;
    const int tx = tid & 15, ty = tid >> 4;
    const int rowBase = blockIdx.y * 64;
    const int colBase = blockIdx.x * 64;
    const int lm  = tid >> 2;
    const int lk  = (tid & 3) * 4;
    const int blk = tid >> 4;
    const int bln = (tid & 15) * 4;
    float acc[4][4] = {};
    for (int kb = 0; kb < 256; kb += 16) {
        int ar = rowBase + lm;
        float4 av = make_float4(0.f, 0.f, 0.f, 0.f);
        if (ar < V_)
            av = *reinterpret_cast<const float4*>(&emb[(size_t)ar * 256 + kb + lk]);
        As[lk + 0][lm] = av.x; As[lk + 1][lm] = av.y;
        As[lk + 2][lm] = av.z; As[lk + 3][lm] = av.w;
        float4 bv = *reinterpret_cast<const float4*>(&Bw[(size_t)(kb + blk) * 256 + colBase + bln]);
        *reinterpret_cast<float4*>(&Bs[blk][bln]) = bv;
        __syncthreads();
#pragma unroll
        for (int k = 0; k < 16; ++k) {
            float4 a4 = *reinterpret_cast<const float4*>(&As[k][ty * 4]);
            float4 b4 = *reinterpret_cast<const float4*>(&Bs[k][tx * 4]);
            float aa[4] = {a4.x, a4.y, a4.z, a4.w};
            float bb[4] = {b4.x, b4.y, b4.z, b4.w};
#pragma unroll
            for (int i = 0; i < 4; ++i)
#pragma unroll
                for (int j = 0; j < 4; ++j)
                    acc[i][j] += aa[i] * bb[j];
        }
        __syncthreads();
    }
#pragma unroll
    for (int i = 0; i < 4; ++i) {
        int r = rowBase + ty * 4 + i;
        if (r < V_)
            *reinterpret_cast<float4*>(&C[(size_t)r * 256 + colBase + tx * 4]) =
                make_float4(acc[i][0], acc[i][1], acc[i][2], acc[i][3]);
    }
}

// ---------------- preamble: 3 weight conversions (single fp16) ----------------
__global__ void conv3(const float* __restrict__ Wz, const float* __restrict__ Wh,
                      const float* __restrict__ Ur)
{
    const float* W; __half* dst;
    switch (blockIdx.y) {
        case 0:  W = Wz + H_ * H_; dst = g_Wzh; break;
        case 1:  W = Wh + H_ * H_; dst = g_Whh; break;
        default: W = Ur;           dst = g_Ur;  break;
    }
    int i = blockIdx.x * 256 + threadIdx.x;
    dst[i] = __float2half_rn(W[i]);
}

// ---------------- per-step gather -> fp16 outputs ------------------------------
__global__ void gather_step(const float* __restrict__ h,
                            const int*   __restrict__ nei,
                            const int*   __restrict__ xids,
                            const float* __restrict__ bur)
{
    const int msg = blockIdx.x * 4 + (threadIdx.x >> 6);
    const int c4  = threadIdx.x & 63;

    // safe (input) reads may precede the dependency sync
    const int xid = xids[msg];
    int jidx[NB_];
#pragma unroll
    for (int n = 0; n < NB_; ++n) jidx[n] = nei[msg * NB_ + n];
    const float4 bu = reinterpret_cast<const float4*>(bur)[c4];

    grid_dep_sync();   // wait for prior step_mma's h / g_hU16 writes

    const float4 er = reinterpret_cast<const float4*>(&g_Er[(size_t)xid * H_])[c4];
    const float bx = er.x + bu.x, by = er.y + bu.y, bz2 = er.z + bu.z, bw = er.w + bu.w;

    float4 sh = make_float4(0.f, 0.f, 0.f, 0.f);
    float4 sg = make_float4(0.f, 0.f, 0.f, 0.f);
#pragma unroll
    for (int n = 0; n < NB_; ++n) {
        const int j = jidx[n];
        const float4 hv = reinterpret_cast<const float4*>(h)[(size_t)j * 64 + c4];
        const uint2 up = reinterpret_cast<const uint2*>(g_hU16)[(size_t)j * 64 + c4];
        const float2 u01 = unpack_h2(up.x);
        const float2 u23 = unpack_h2(up.y);
        sh.x += hv.x; sh.y += hv.y; sh.z += hv.z; sh.w += hv.w;
        sg.x += sigf(bx  + u01.x) * hv.x;
        sg.y += sigf(by  + u01.y) * hv.y;
        sg.z += sigf(bz2 + u23.x) * hv.z;
        sg.w += sigf(bw  + u23.y) * hv.w;
    }
    const size_t o4 = (size_t)msg * 64 + c4;
    {
        __half h0 = __float2half_rn(sh.x), h1 = __float2half_rn(sh.y),
               h2 = __float2half_rn(sh.z), h3 = __float2half_rn(sh.w);
        uint2 u;
        { __half2 a; a.x = h0; a.y = h1; u.x = *reinterpret_cast<uint32_t*>(&a); }
        { __half2 a; a.x = h2; a.y = h3; u.y = *reinterpret_cast<uint32_t*>(&a); }
        reinterpret_cast<uint2*>(g_sh_hi)[o4] = u;
        uint2 v;
        v.x = pack_h2(sh.x - __half2float(h0), sh.y - __half2float(h1));
        v.y = pack_h2(sh.z - __half2float(h2), sh.w - __half2float(h3));
        reinterpret_cast<uint2*>(g_sh_lo)[o4] = v;
    }
    {
        uint2 u;
        u.x = pack_h2(sg.x, sg.y);
        u.y = pack_h2(sg.z, sg.w);
        reinterpret_cast<uint2*>(g_sg)[o4] = u;
    }
}

// ---------------- fused step GEMM: BM=64, BN=256, 512 threads -----------------
// 16 warps = 2(M) x 8(N); warp tile 32x32. Single-term fp16.
// Passes 1+2 fused in ONE k-loop (dual A, dual B).
#define A_STRIDE  40     // 32 + 8 pad (fp16)
#define BW_STRIDE 264    // 256 + 8 pad
#define NH_STRIDE 264

#define ST_A1    0                // 64*40*2  = 5120
#define ST_A2    5120
#define ST_B1    10240            // 32*264*2 = 16896
#define ST_B2    27136
#define ST_SZ    44032            // per stage
#define P_SZ     (2*ST_SZ)        // 88064
#define U_ST_SZ  16896            // pass3 stage (Ur only), double-buffered at base
#define NH_OFF   P_SZ             // 88064, size 64*264*2 = 33792
#define SM_TOTAL (P_SZ + 33792)   // 121856 bytes

// fused dual pass over K=256: acc1 += A1 @ B1, acc2 += A2 @ B2
__device__ __forceinline__ void pass_AB2(
    const __half* __restrict__ A1, const __half* __restrict__ A2,
    const __half* __restrict__ B1, const __half* __restrict__ B2,
    int rowBase, float acc1[2][4][4], float acc2[2][4][4], uint32_t sbase)
{
    const int tid  = threadIdx.x;
    const int lane = tid & 31;
    const int wid  = tid >> 5;
    const int warp_m = wid & 1;
    const int warp_n = wid >> 1;   // 0..7

    const int  asel = tid >> 8;          // 0 or 1
    const int  arow = (tid & 255) >> 2;  // 0..63
    const int  ak   = (tid & 3) * 8;
    const uint32_t a_soff = (asel ? ST_A2 : ST_A1) + (uint32_t)(arow * A_STRIDE + ak) * 2;
    const __half* Ag = asel ? A2 : A1;
    const size_t a_goff = (size_t)(rowBase + arow) * 256 + ak;

    const int brow = tid >> 4;           // 0..31
    const int bcol = (tid & 15) * 8;     // 0..120
    const uint32_t b_soff0 = (uint32_t)(brow * BW_STRIDE + bcol) * 2;
    const uint32_t b_soff1 = (uint32_t)(brow * BW_STRIDE + bcol + 128) * 2;
    const size_t b_goff = (size_t)brow * 256 + bcol;

    cpa16(sbase + a_soff, &Ag[a_goff]);
    cpa16(sbase + ST_B1 + b_soff0, &B1[b_goff]);
    cpa16(sbase + ST_B1 + b_soff1, &B1[b_goff + 128]);
    cpa16(sbase + ST_B2 + b_soff0, &B2[b_goff]);
    cpa16(sbase + ST_B2 + b_soff1, &B2[b_goff + 128]);
    CP_COMMIT();

    for (int it = 0; it < 8; ++it) {
        const uint32_t scur = sbase + (uint32_t)(it & 1) * ST_SZ;
        __syncthreads();
        if (it < 7) {
            const uint32_t snxt = sbase + (uint32_t)((it + 1) & 1) * ST_SZ;
            const int kb = (it + 1) * 32;
            cpa16(snxt + a_soff, &Ag[a_goff + kb]);
            cpa16(snxt + ST_B1 + b_soff0, &B1[b_goff + (size_t)kb * 256]);
            cpa16(snxt + ST_B1 + b_soff1, &B1[b_goff + (size_t)kb * 256 + 128]);
            cpa16(snxt + ST_B2 + b_soff0, &B2[b_goff + (size_t)kb * 256]);
            cpa16(snxt + ST_B2 + b_soff1, &B2[b_goff + (size_t)kb * 256 + 128]);
        }
        CP_COMMIT();
        CP_WAIT1();
        __syncthreads();

#pragma unroll
        for (int ks = 0; ks < 32; ks += 16) {
            uint32_t a1_[2][4], a2_[2][4];
#pragma unroll
            for (int mt = 0; mt < 2; ++mt) {
                const int el = (warp_m * 32 + mt * 16 + (lane & 15)) * A_STRIDE
                             + ks + (lane >> 4) * 8;
                ldsm4(a1_[mt], scur + ST_A1 + el * 2);
                ldsm4(a2_[mt], scur + ST_A2 + el * 2);
            }
#pragma unroll
            for (int np = 0; np < 2; ++np) {
                const int n0 = warp_n * 32 + np * 16;
                const int el = (ks + (lane & 7) + ((lane >> 3) & 1) * 8) * BW_STRIDE
                             + n0 + (lane >> 4) * 8;
                uint32_t b1_[4], b2_[4];
                ldsm4t(b1_, scur + ST_B1 + el * 2);
                ldsm4t(b2_, scur + ST_B2 + el * 2);
#pragma unroll
                for (int mt = 0; mt < 2; ++mt) {
#pragma unroll
                    for (int s = 0; s < 2; ++s) {
                        mma16816(acc1[mt][np * 2 + s], a1_[mt], &b1_[2 * s]);
                        mma16816(acc2[mt][np * 2 + s], a2_[mt], &b2_[2 * s]);
                    }
                }
            }
        }
    }
}

// pass3: acc += new_h(smem fp16) @ Ur(fp16)
__device__ __forceinline__ void pass_U(float acc[2][4][4], uint32_t sbase)
{
    const int tid  = threadIdx.x;
    const int lane = tid & 31;
    const int wid  = tid >> 5;
    const int warp_m = wid & 1;
    const int warp_n = wid >> 1;

    const int brow = tid >> 4;
    const int bcol = (tid & 15) * 8;
    const uint32_t b_soff0 = (uint32_t)(brow * BW_STRIDE + bcol) * 2;
    const uint32_t b_soff1 = (uint32_t)(brow * BW_STRIDE + bcol + 128) * 2;
    const size_t b_goff = (size_t)brow * 256 + bcol;

    cpa16(sbase + b_soff0, &g_Ur[b_goff]);
    cpa16(sbase + b_soff1, &g_Ur[b_goff + 128]);
    CP_COMMIT();

    for (int it = 0; it < 8; ++it) {
        const uint32_t scur = sbase + (uint32_t)(it & 1) * U_ST_SZ;
        __syncthreads();
        if (it < 7) {
            const uint32_t snxt = sbase + (uint32_t)((it + 1) & 1) * U_ST_SZ;
            const int kb = (it + 1) * 32;
            cpa16(snxt + b_soff0, &g_Ur[b_goff + (size_t)kb * 256]);
            cpa16(snxt + b_soff1, &g_Ur[b_goff + (size_t)kb * 256 + 128]);
        }
        CP_COMMIT();
        CP_WAIT1();
        __syncthreads();

        const int kb = it * 32;
#pragma unroll
        for (int ks = 0; ks < 32; ks += 16) {
            uint32_t a_[2][4];
#pragma unroll
            for (int mt = 0; mt < 2; ++mt) {
                const int el = (warp_m * 32 + mt * 16 + (lane & 15)) * NH_STRIDE
                             + kb + ks + (lane >> 4) * 8;
                ldsm4(a_[mt], sbase + NH_OFF + el * 2);
            }
#pragma unroll
            for (int np = 0; np < 2; ++np) {
                const int n0 = warp_n * 32 + np * 16;
                const int el = (ks + (lane & 7) + ((lane >> 3) & 1) * 8) * BW_STRIDE
                             + n0 + (lane >> 4) * 8;
                uint32_t bh_[4];
                ldsm4t(bh_, scur + el * 2);
#pragma unroll
                for (int mt = 0; mt < 2; ++mt) {
#pragma unroll
                    for (int s = 0; s < 2; ++s)
                        mma16816(acc[mt][np * 2 + s], a_[mt], &bh_[2 * s]);
                }
            }
        }
    }
}

__global__ void __launch_bounds__(512, 1) step_mma(
    const float* __restrict__ bz, const float* __restrict__ bhb,
    const int*   __restrict__ xids,
    float* __restrict__ hout, __half* __restrict__ hUout, int first)
{
    extern __shared__ char dsm[];
    const uint32_t sbase = smem_u32(dsm);
    const int rowBase = blockIdx.x * 64;

    grid_dep_sync();   // wait for prior gather's sum-buffer writes (or preamble at t=0)

    float acc1[2][4][4] = {};
    float acc2[2][4][4] = {};
    if (!first)
        pass_AB2(g_sh_hi, g_sg, g_Wzh, g_Whh, rowBase, acc1, acc2, sbase);

    const int lane = threadIdx.x & 31;
    const int wid  = threadIdx.x >> 5;
    const int warp_m = wid & 1, warp_n = wid >> 1;

    // GRU epilogue -> hout (global fp32) + new_h fp16 into smem (NH region)
#pragma unroll
    for (int mt = 0; mt < 2; ++mt) {
#pragma unroll
        for (int nt = 0; nt < 4; ++nt) {
            const int col = warp_n * 32 + nt * 8 + (lane & 3) * 2;
#pragma unroll
            for (int half = 0; half < 2; ++half) {
                const int lr = warp_m * 32 + mt * 16 + (lane >> 2) + half * 8;
                const int r  = rowBase + lr;
                const float a1x = acc1[mt][nt][half * 2 + 0];
                const float a1y = acc1[mt][nt][half * 2 + 1];
                const float a2x = acc2[mt][nt][half * 2 + 0];
                const float a2y = acc2[mt][nt][half * 2 + 1];
                const int xid = xids[r];
                const float2 ez  = *reinterpret_cast<const float2*>(&g_Ez[(size_t)xid * H_ + col]);
                const float2 eh  = *reinterpret_cast<const float2*>(&g_Eh[(size_t)xid * H_ + col]);
                const float2 bzv = *reinterpret_cast<const float2*>(&bz[col]);
                const float2 bhv = *reinterpret_cast<const float2*>(&bhb[col]);
                float sh0 = 0.f, sh1 = 0.f;
                if (!first) {
                    const uint32_t shh = *reinterpret_cast<const uint32_t*>(&g_sh_hi[(size_t)r * H_ + col]);
                    const uint32_t shl = *reinterpret_cast<const uint32_t*>(&g_sh_lo[(size_t)r * H_ + col]);
                    const float2 sh_h = unpack_h2(shh);
                    const float2 sh_l = unpack_h2(shl);
                    sh0 = sh_h.x + sh_l.x;
                    sh1 = sh_h.y + sh_l.y;
                }
                const float z0 = sigf(ez.x + bzv.x + a1x);
                const float z1 = sigf(ez.y + bzv.y + a1y);
                const float p0 = tanha(eh.x + bhv.x + a2x);
                const float p1 = tanha(eh.y + bhv.y + a2y);
                const float o0 = (1.0f - z0) * sh0 + z0 * p0;
                const float o1 = (1.0f - z1) * sh1 + z1 * p1;
                *reinterpret_cast<float2*>(&hout[(size_t)r * H_ + col]) = make_float2(o0, o1);
                const uint32_t soff = (uint32_t)(lr * NH_STRIDE + col) * 2;
                __half2 hp; hp.x = __float2half_rn(o0); hp.y = __float2half_rn(o1);
                *reinterpret_cast<__half2*>(dsm + NH_OFF + soff) = hp;
            }
        }
    }

    // pass3: hU = new_h @ Ur (A from smem), store fp16
    float acc3[2][4][4] = {};
    pass_U(acc3, sbase);

#pragma unroll
    for (int mt = 0; mt < 2; ++mt) {
#pragma unroll
        for (int nt = 0; nt < 4; ++nt) {
            const int col = warp_n * 32 + nt * 8 + (lane & 3) * 2;
            const int r0  = rowBase + warp_m * 32 + mt * 16 + (lane >> 2);
            __half2 u0; u0.x = __float2half_rn(acc3[mt][nt][0]);
                        u0.y = __float2half_rn(acc3[mt][nt][1]);
            *reinterpret_cast<__half2*>(&hUout[(size_t)r0 * H_ + col]) = u0;
            __half2 u1; u1.x = __float2half_rn(acc3[mt][nt][2]);
                        u1.y = __float2half_rn(acc3[mt][nt][3]);
            *reinterpret_cast<__half2*>(&hUout[(size_t)(r0 + 8) * H_ + col]) = u1;
        }
    }
}

// ---------------- fused root aggregate ----------------------------------------
__global__ void root_fused(const float* __restrict__ h, const int* __restrict__ rnei,
                           const int* __restrict__ rwid, const float* __restrict__ Woh,
                           const float* __restrict__ bo, float* __restrict__ out)
{
    __shared__ float s_sum[256];
    __shared__ int sj[NB_];
    const int b = blockIdx.x;
    const int c = threadIdx.x;
    if (c < NB_) sj[c] = rnei[b * NB_ + c];
    __syncthreads();
    float s = 0.f;
#pragma unroll
    for (int n = 0; n < NB_; ++n)
        s += h[(size_t)sj[n] * 256 + c];
    s_sum[c] = s;
    __syncthreads();
    float acc = 0.f;
#pragma unroll 8
    for (int k = 0; k < 256; ++k)
        acc += s_sum[k] * Woh[(size_t)k * 256 + c];
    const int xid = rwid[b];
    float v = g_Eo[(size_t)xid * 256 + c] + bo[c] + acc;
    out[(size_t)b * 256 + c] = fmaxf(v, 0.0f);
}

// ---------------- launch ------------------------------------------------------
extern "C" void kernel_launch(void* const* d_in, const int* in_sizes, int n_in,
                              void* d_out, int out_size)
{
    const int*   x_ids    = (const int*)  d_in[0];
    const int*   nei_idx  = (const int*)  d_in[1];
    const int*   root_wid = (const int*)  d_in[2];
    const int*   root_nei = (const int*)  d_in[3];
    const float* emb      = (const float*)d_in[4];
    const float* Wz       = (const float*)d_in[5];
    const float* bz       = (const float*)d_in[6];
    const float* Wr       = (const float*)d_in[7];
    const float* Ur       = (const float*)d_in[8];
    const float* bur      = (const float*)d_in[9];
    const float* Wh       = (const float*)d_in[10];
    const float* bh       = (const float*)d_in[11];
    const float* Wo       = (const float*)d_in[12];
    const float* bo       = (const float*)d_in[13];

    float* out  = (float*)d_out;
    float* h    = out;
    float* rvec = out + (size_t)(M_ + 1) * H_;

    __half* p_hU16;
    cudaGetSymbolAddress((void**)&p_hU16, g_hU16);

    cudaFuncSetAttribute(step_mma, cudaFuncAttributeMaxDynamicSharedMemorySize, SM_TOTAL);

    init_zero<<<1, 256>>>(h);

    dim3 gpre(4, (V_ + 63) / 64, 4);
    gemm_pre<<<gpre, 256>>>(emb, Wz, Wr, Wh, Wo);
    conv3<<<dim3(256, 3), 256>>>(Wz, Wh, Ur);

    // PDL launch configs (programmatic stream serialization)
    cudaLaunchAttribute pdl[1];
    pdl[0].id = cudaLaunchAttributeProgrammaticStreamSerialization;
    pdl[0].val.programmaticStreamSerializationAllowed = 1;

    cudaLaunchConfig_t gcfg = {};
    gcfg.gridDim = dim3(E_ / 4); gcfg.blockDim = dim3(256);
    gcfg.dynamicSmemBytes = 0; gcfg.stream = 0;
    gcfg.attrs = pdl; gcfg.numAttrs = 1;

    cudaLaunchConfig_t scfg = {};
    scfg.gridDim = dim3(E_ / 64); scfg.blockDim = dim3(512);
    scfg.dynamicSmemBytes = SM_TOTAL; scfg.stream = 0;
    scfg.attrs = pdl; scfg.numAttrs = 1;

    for (int t = 0; t < T_; ++t) {
        if (t > 0) {
            const int* nei_t  = nei_idx + (size_t)t * E_ * NB_;
            const int* xids_t = x_ids + (size_t)t * E_;
            cudaLaunchKernelEx(&gcfg, gather_step, (const float*)h, nei_t, xids_t, bur);
        }
        const int* xids_t = x_ids + (size_t)t * E_;
        float*  hout_t = h + (size_t)(1 + t * E_) * H_;
        __half* hU_t   = p_hU16 + (size_t)(1 + t * E_) * H_;
        int first = (t == 0) ? 1 : 0;
        cudaLaunchKernelEx(&scfg, step_mma, (const float*)bz, (const float*)bh,
                           xids_t, hout_t, hU_t, first);
    }

    root_fused<<<B_, 256>>>(h, root_nei, root_wid, Wo + (size_t)H_ * H_, bo, rvec);
}